// round 3
// baseline (speedup 1.0000x reference)
#include <cuda_runtime.h>
#include <cuda_bf16.h>

// Problem shapes (fixed by setup_inputs)
#define B_      4
#define L_      8192
#define BLOCK_  128
#define NB_     (L_ / BLOCK_)          // 64
#define V_      32000
#define D_      1024
#define NT_     (L_ + NB_)             // 8256 new_tokens per batch row

// Output layout (flattened tuple, row-major, float32):
//   [0,        B*NT)                new_tokens      (33024)
//   [OFF_CE,   OFF_CE + B*NB*D)     cat_emb         (262144)
//   [OFF_H,    OFF_H  + B*NB*V)     hist            (8192000)
#define OFF_CE  (B_ * NT_)                         // 33024
#define OFF_H   (OFF_CE + B_ * NB_ * D_)           // 295168

#define HIST_F4   ((B_ * NB_ * V_) / 4)            // 2,048,000 float4
#define ZERO_CTAS 1024
#define GRID1     (ZERO_CTAS + B_ * NB_)           // 1024 + 256 = 1280

// K1: wide-grid zero-fill of hist region + cat_emb gather + new_tokens.
__global__ __launch_bounds__(256)
void chunk_agg_fill(const int* __restrict__ tokens,
                    const float* __restrict__ catW,
                    float* __restrict__ out)
{
    const int bid = blockIdx.x;
    const int tid = threadIdx.x;

    if (bid < ZERO_CTAS) {
        // Zero the entire hist region with a full-occupancy grid-stride loop.
        // ~7.8 float4 per thread -> MLP ~8 outstanding stores each.
        float4* __restrict__ h4 = reinterpret_cast<float4*>(out + OFF_H);
        const float4 z4 = make_float4(0.f, 0.f, 0.f, 0.f);
        #pragma unroll 4
        for (int i = bid * 256 + tid; i < HIST_F4; i += ZERO_CTAS * 256)
            h4[i] = z4;
    } else {
        // One CTA per (b, j) block: embed row copy + new_tokens writes.
        const int bj = bid - ZERO_CTAS;      // 0..255
        const int b  = bj >> 6;
        const int j  = bj & 63;
        const int* __restrict__ blk = tokens + b * L_ + j * BLOCK_;
        const int t0 = blk[0];

        const float4* __restrict__ src =
            reinterpret_cast<const float4*>(catW + (size_t)t0 * D_);
        float4* __restrict__ dst =
            reinterpret_cast<float4*>(out + OFF_CE + bj * D_);
        dst[tid] = src[tid];                 // 1024 f32 = 256 float4

        if (tid < BLOCK_)
            out[b * NT_ + NB_ + j * BLOCK_ + tid] = (float)blk[tid];
        if (tid == 0)
            out[b * NT_ + j] = (float)t0;
    }
}

// K2: histogram scatter — one fire-and-forget atomic per token (REDG path).
__global__ __launch_bounds__(1024)
void chunk_agg_scatter(const int* __restrict__ tokens,
                       float* __restrict__ out)
{
    const int g  = blockIdx.x * 1024 + threadIdx.x;   // 0..32767 (= B*L)
    const int bj = g >> 7;                            // token-block index
    atomicAdd(out + OFF_H + (size_t)bj * V_ + tokens[g], 1.0f);
}

extern "C" void kernel_launch(void* const* d_in, const int* in_sizes, int n_in,
                              void* d_out, int out_size)
{
    const int*   tokens = (const int*)  d_in[0];   // [4, 8192] int32
    const float* catW   = (const float*)d_in[1];   // [32000, 1024] f32
    // d_in[2] (num_embed_W) is a dead lookup in the reference — unused.
    float* out = (float*)d_out;

    chunk_agg_fill<<<GRID1, 256>>>(tokens, catW, out);
    chunk_agg_scatter<<<(B_ * L_) / 1024, 1024>>>(tokens, out);
}

// round 5
// speedup vs baseline: 1.1254x; 1.1254x over previous
#include <cuda_runtime.h>
#include <cuda_bf16.h>

// Problem shapes (fixed by setup_inputs)
#define B_      4
#define L_      8192
#define BLOCK_  128
#define NB_     (L_ / BLOCK_)          // 64
#define V_      32000
#define D_      1024
#define NT_     (L_ + NB_)             // 8256 new_tokens per batch row

// Output layout (flattened tuple, row-major, float32):
//   [0,        B*NT)                new_tokens      (33024)
//   [OFF_CE,   OFF_CE + B*NB*D)     cat_emb         (262144)
//   [OFF_H,    OFF_H  + B*NB*V)     hist            (8192000)
#define OFF_CE  (B_ * NT_)                         // 33024
#define OFF_H   (OFF_CE + B_ * NB_ * D_)           // 295168

#define QUARTERS 4
#define QF32     (V_ / QUARTERS)                   // 8000 f32 per quarter
#define QF4      (QF32 / 4)                        // 2000 float4 per quarter
#define GRID_    (B_ * NB_ * QUARTERS)             // 1024 CTAs

// One fused kernel. CTA (bj, q):
//   1. zero quarter q of hist slice bj  (disjoint across CTAs)
//   2. __syncthreads (orders this CTA's global stores for this CTA's threads)
//   3. scatter the block's tokens whose value lies in this quarter's range
//   4. (q==0 only) cat_emb row copy + new_tokens writes
__global__ __launch_bounds__(256)
void chunk_agg_fused(const int* __restrict__ tokens,
                     const float* __restrict__ catW,
                     float* __restrict__ out)
{
    const int bid = blockIdx.x;
    const int q   = bid & (QUARTERS - 1);
    const int bj  = bid >> 2;            // 0..255
    const int b   = bj >> 6;
    const int j   = bj & 63;
    const int tid = threadIdx.x;

    float* __restrict__ hist = out + OFF_H + (size_t)bj * V_;

    // ---- 1) zero this CTA's private quarter (2000 float4, ~8 per thread)
    {
        float4* __restrict__ h4 =
            reinterpret_cast<float4*>(hist + q * QF32);
        const float4 z4 = make_float4(0.f, 0.f, 0.f, 0.f);
        #pragma unroll 4
        for (int i = tid; i < QF4; i += 256)
            h4[i] = z4;
    }

    // ---- 4) side outputs (only one CTA per slice; overlaps with zeroing wave)
    const int* __restrict__ blk = tokens + b * L_ + j * BLOCK_;
    if (q == 0) {
        const int t0 = blk[0];
        const float4* __restrict__ src =
            reinterpret_cast<const float4*>(catW + (size_t)t0 * D_);
        float4* __restrict__ dst =
            reinterpret_cast<float4*>(out + OFF_CE + bj * D_);
        dst[tid] = src[tid];             // 1024 f32 = 256 float4

        if (tid < BLOCK_)
            out[b * NT_ + NB_ + j * BLOCK_ + tid] = (float)blk[tid];
        if (tid == 0)
            out[b * NT_ + j] = (float)t0;
    }

    // ---- 2+3) scatter tokens belonging to this quarter's range
    __syncthreads();
    if (tid < BLOCK_) {
        const int tok = blk[tid];
        const int lo  = q * QF32;
        if (tok >= lo && tok < lo + QF32)
            atomicAdd(&hist[tok], 1.0f);
    }
}

extern "C" void kernel_launch(void* const* d_in, const int* in_sizes, int n_in,
                              void* d_out, int out_size)
{
    const int*   tokens = (const int*)  d_in[0];   // [4, 8192] int32
    const float* catW   = (const float*)d_in[1];   // [32000, 1024] f32
    // d_in[2] (num_embed_W) is a dead lookup in the reference — unused.
    float* out = (float*)d_out;

    chunk_agg_fused<<<GRID_, 256>>>(tokens, catW, out);
}

// round 6
// speedup vs baseline: 1.1488x; 1.0208x over previous
#include <cuda_runtime.h>
#include <cuda_bf16.h>

// Problem shapes (fixed by setup_inputs)
#define B_      4
#define L_      8192
#define BLOCK_  128
#define NB_     (L_ / BLOCK_)          // 64
#define V_      32000
#define D_      1024
#define NT_     (L_ + NB_)             // 8256 new_tokens per batch row

// Output layout (flattened tuple, row-major, float32):
//   [0,        B*NT)                new_tokens      (33024)
//   [OFF_CE,   OFF_CE + B*NB*D)     cat_emb         (262144)
//   [OFF_H,    OFF_H  + B*NB*V)     hist            (8192000)
#define OFF_CE  (B_ * NT_)                         // 33024
#define OFF_H   (OFF_CE + B_ * NB_ * D_)           // 295168

#define QUARTERS 4
#define QF32     (V_ / QUARTERS)                   // 8000 bins per quarter
#define QF4      (QF32 / 4)                        // 2000 float4 per quarter
#define GRID_    (B_ * NB_ * QUARTERS)             // 1024 CTAs, one wave @ 7/SM

// One fused kernel, no global atomics. CTA (bj, q):
//   1. zero a 32 KB SMEM count array (8000 floats)
//   2. shared atomicAdd the block's tokens that fall in this quarter's range
//   3. stream the final slice quarter to global: LDS.128 -> STG.128
//   4. (q==0 only) cat_emb row copy + new_tokens writes (overlapped)
__global__ __launch_bounds__(256)
void chunk_agg_smem(const int* __restrict__ tokens,
                    const float* __restrict__ catW,
                    float* __restrict__ out)
{
    __shared__ float cnt[QF32];          // 32 KB

    const int bid = blockIdx.x;
    const int q   = bid & (QUARTERS - 1);
    const int bj  = bid >> 2;            // 0..255
    const int b   = bj >> 6;
    const int j   = bj & 63;
    const int tid = threadIdx.x;

    // ---- 1) zero SMEM counts (8000 floats, ~31 per thread as float4)
    {
        float4* c4 = reinterpret_cast<float4*>(cnt);
        const float4 z4 = make_float4(0.f, 0.f, 0.f, 0.f);
        #pragma unroll
        for (int i = tid; i < QF4; i += 256)
            c4[i] = z4;
    }

    const int* __restrict__ blk = tokens + b * L_ + j * BLOCK_;

    // ---- 4) side outputs (only q==0 CTA of each slice; stores are
    //         fire-and-forget and overlap with the rest of the CTA's work)
    if (q == 0) {
        const int t0 = blk[0];
        const float4* __restrict__ src =
            reinterpret_cast<const float4*>(catW + (size_t)t0 * D_);
        float4* __restrict__ dst =
            reinterpret_cast<float4*>(out + OFF_CE + bj * D_);
        dst[tid] = src[tid];             // 1024 f32 = 256 float4

        if (tid < BLOCK_)
            out[b * NT_ + NB_ + j * BLOCK_ + tid] = (float)blk[tid];
        if (tid == 0)
            out[b * NT_ + j] = (float)t0;
    }

    __syncthreads();

    // ---- 2) count into SMEM (spread-address shared atomics, ~2 cyc/lane)
    if (tid < BLOCK_) {
        const int tok = blk[tid];
        const int lo  = q * QF32;
        if (tok >= lo && tok < lo + QF32)
            atomicAdd(&cnt[tok - lo], 1.0f);
    }

    __syncthreads();

    // ---- 3) stream final values to global: one clean 8 KB-per-CTA-iter
    //         write stream, no read-modify-write, no global atomics.
    {
        float* __restrict__ hist =
            out + OFF_H + (size_t)bj * V_ + q * QF32;
        float4* __restrict__ h4 = reinterpret_cast<float4*>(hist);
        const float4* c4 = reinterpret_cast<const float4*>(cnt);
        #pragma unroll 4
        for (int i = tid; i < QF4; i += 256)
            h4[i] = c4[i];
    }
}

extern "C" void kernel_launch(void* const* d_in, const int* in_sizes, int n_in,
                              void* d_out, int out_size)
{
    const int*   tokens = (const int*)  d_in[0];   // [4, 8192] int32
    const float* catW   = (const float*)d_in[1];   // [32000, 1024] f32
    // d_in[2] (num_embed_W) is a dead lookup in the reference — unused.
    float* out = (float*)d_out;

    chunk_agg_smem<<<GRID_, 256>>>(tokens, catW, out);
}

// round 8
// speedup vs baseline: 1.1522x; 1.0030x over previous
#include <cuda_runtime.h>
#include <cuda_bf16.h>
#include <cstdint>

// Problem shapes (fixed by setup_inputs)
#define B_      4
#define L_      8192
#define BLOCK_  128
#define NB_     (L_ / BLOCK_)          // 64
#define V_      32000
#define D_      1024
#define NT_     (L_ + NB_)             // 8256 new_tokens per batch row

// Output layout (flattened tuple, row-major, float32):
//   [0,        B*NT)                new_tokens      (33024)
//   [OFF_CE,   OFF_CE + B*NB*D)     cat_emb         (262144)
//   [OFF_H,    OFF_H  + B*NB*V)     hist            (8192000)
#define OFF_CE  (B_ * NT_)                         // 33024
#define OFF_H   (OFF_CE + B_ * NB_ * D_)           // 295168

#define QUARTERS 4
#define QF32     (V_ / QUARTERS)                   // 8000 bins per quarter
#define QF4      (QF32 / 4)                        // 2000 float4 per quarter
#define QBYTES   (QF32 * 4)                        // 32000 bytes (16B multiple)
#define GRID_    (B_ * NB_ * QUARTERS)             // 1024 CTAs

// Fused kernel, hist drained via TMA bulk store (UTMASTG) instead of STG.
// CTA (bj, q):
//   1. zero 32 KB SMEM count array
//   2. shared atomicAdd tokens in this quarter's range
//   3. fence.proxy.async + one cp.async.bulk SMEM -> GMEM (32 KB)
//   4. (q==0) cat_emb row copy + new_tokens via scalar stores
__global__ __launch_bounds__(256)
void chunk_agg_tma(const int* __restrict__ tokens,
                   const float* __restrict__ catW,
                   float* __restrict__ out)
{
    __shared__ float cnt[QF32];          // 32 KB

    const int bid = blockIdx.x;
    const int q   = bid & (QUARTERS - 1);
    const int bj  = bid >> 2;            // 0..255
    const int b   = bj >> 6;
    const int j   = bj & 63;
    const int tid = threadIdx.x;

    // ---- 1) zero SMEM counts (2000 float4, ~8 per thread)
    {
        float4* c4 = reinterpret_cast<float4*>(cnt);
        const float4 z4 = make_float4(0.f, 0.f, 0.f, 0.f);
        #pragma unroll
        for (int i = tid; i < QF4; i += 256)
            c4[i] = z4;
    }

    const int* __restrict__ blk = tokens + b * L_ + j * BLOCK_;

    // ---- 4) side outputs (q==0 CTA only; small, fire-and-forget STG)
    if (q == 0) {
        const int t0 = blk[0];
        const float4* __restrict__ src =
            reinterpret_cast<const float4*>(catW + (size_t)t0 * D_);
        float4* __restrict__ dst =
            reinterpret_cast<float4*>(out + OFF_CE + bj * D_);
        dst[tid] = src[tid];             // 1024 f32 = 256 float4

        if (tid < BLOCK_)
            out[b * NT_ + NB_ + j * BLOCK_ + tid] = (float)blk[tid];
        if (tid == 0)
            out[b * NT_ + j] = (float)t0;
    }

    __syncthreads();

    // ---- 2) count into SMEM (spread-address shared atomics)
    if (tid < BLOCK_) {
        const int tok = blk[tid];
        const int lo  = q * QF32;
        if (tok >= lo && tok < lo + QF32)
            atomicAdd(&cnt[tok - lo], 1.0f);
    }

    __syncthreads();

    // ---- 3) drain the quarter to global with ONE TMA bulk store.
    if (tid == 0) {
        // make generic-proxy SMEM writes (STS + atomicS) visible to async proxy
        asm volatile("fence.proxy.async.shared::cta;" ::: "memory");

        uint32_t saddr;
        asm("{ .reg .u64 t; cvta.to.shared.u64 t, %1; cvt.u32.u64 %0, t; }"
            : "=r"(saddr) : "l"(cnt));
        float* gdst = out + OFF_H + (size_t)bj * V_ + q * QF32;

        asm volatile(
            "cp.async.bulk.global.shared::cta.bulk_group [%0], [%1], %2;"
            :: "l"(gdst), "r"(saddr), "n"(QBYTES) : "memory");
        asm volatile("cp.async.bulk.commit_group;" ::: "memory");
        // hold SMEM alive until the TMA engine has read it
        asm volatile("cp.async.bulk.wait_group.read 0;" ::: "memory");
    }
}

extern "C" void kernel_launch(void* const* d_in, const int* in_sizes, int n_in,
                              void* d_out, int out_size)
{
    const int*   tokens = (const int*)  d_in[0];   // [4, 8192] int32
    const float* catW   = (const float*)d_in[1];   // [32000, 1024] f32
    // d_in[2] (num_embed_W) is a dead lookup in the reference — unused.
    float* out = (float*)d_out;

    chunk_agg_tma<<<GRID_, 256>>>(tokens, catW, out);
}